// round 15
// baseline (speedup 1.0000x reference)
#include <cuda_runtime.h>
#include <cuda_fp16.h>
#include <cstdint>

#define DEV __device__ __forceinline__

// problem dims
#define N_IMG 256
#define D_INF 768
#define D_HID 768
#define D_OUTF 512
#define M_GAL 100000
#define TOPK 5

// scratch (no cudaMalloc allowed)
__device__ __half g_Ahi2[N_IMG*D_HID];
__device__ __half g_Alo2[N_IMG*D_HID];
__device__ float  g_IMG [N_IMG*D_OUTF];
__device__ __half g_AN  [N_IMG*D_OUTF];
// topk scratch
__device__ float g_pmax[100];
__device__ float g_psum[100];
__device__ int   g_pidx[100*TOPK];
__device__ float g_pval[100*TOPK];

DEV void cp16(void* s, const void* g){
  uint32_t sa = (uint32_t)__cvta_generic_to_shared(s);
  asm volatile("cp.async.cg.shared.global [%0], [%1], 16;" :: "r"(sa), "l"(g));
}
DEV void cp_commit(){ asm volatile("cp.async.commit_group;"); }
DEV void cp_wait0(){ asm volatile("cp.async.wait_group 0;"); }

DEV void ldsm4(uint32_t* d, const void* p){
  uint32_t a=(uint32_t)__cvta_generic_to_shared(p);
  asm volatile("ldmatrix.sync.aligned.m8n8.x4.shared.b16 {%0,%1,%2,%3}, [%4];"
    : "=r"(d[0]),"=r"(d[1]),"=r"(d[2]),"=r"(d[3]) : "r"(a));
}
DEV void mma_fp16(float* c, const uint32_t* a, const uint32_t* b){
  asm volatile("mma.sync.aligned.m16n8k16.row.col.f32.f16.f16.f32 "
    "{%0,%1,%2,%3}, {%4,%5,%6,%7}, {%8,%9}, {%0,%1,%2,%3};"
    : "+f"(c[0]),"+f"(c[1]),"+f"(c[2]),"+f"(c[3])
    : "r"(a[0]),"r"(a[1]),"r"(a[2]),"r"(a[3]),"r"(b[0]),"r"(b[1]));
}

// ===== MLP GEMM (round-12 proven): 3-term fp16, BM=32 BN=64 BK=64, 2-stage =====
template<bool A_F32, bool RELU, bool SPLIT>
__global__ __launch_bounds__(256, 2)
void mlpgemm(const float* __restrict__ Af, const __half* __restrict__ Ahi, const __half* __restrict__ Alo,
             const float* __restrict__ B, const float* __restrict__ bias,
             float* __restrict__ Cf, __half* __restrict__ Chi, __half* __restrict__ Clo,
             int Ntot, int K){
  constexpr int SABB = 144;
  constexpr int ABY  = 32*SABB;
  constexpr int OB   = 2*ABY;
  constexpr int BBY  = 64*SABB;
  constexpr int STAGE= OB + 2*BBY;   // 27648 ; x2 = 55296

  extern __shared__ __align__(16) char sm[];
  const int tid = threadIdx.x, lane = tid & 31, warp = tid >> 5;
  const int wm = (warp & 1) * 16, wn = (warp >> 1) * 16;
  const int m0 = blockIdx.x * 32, n0 = blockIdx.y * 64;
  const int nch = K / 64;

  float acc[2][4];
#pragma unroll
  for (int b=0;b<2;b++)
#pragma unroll
    for (int c=0;c<4;c++) acc[b][c]=0.f;

  float4 breg[2][2];
  float4 areg[2];
  auto loadB = [&](int kb){
#pragma unroll
    for (int s=0;s<2;s++){
      int seg = tid + s*256;
      int row = seg >> 3, sc = seg & 7;
      const float4* p = reinterpret_cast<const float4*>(B + (size_t)(n0+row)*K + kb + sc*8);
      breg[s][0] = p[0]; breg[s][1] = p[1];
    }
  };
  auto loadA = [&](int kb){
    int row = tid >> 3, sc = tid & 7;
    const float4* p = reinterpret_cast<const float4*>(Af + (size_t)(m0+row)*K + kb + sc*8);
    areg[0] = p[0]; areg[1] = p[1];
  };
  auto split8 = [&](const float4& a, const float4& b, uint4& uh, uint4& ul){
    float f[8] = {a.x,a.y,a.z,a.w,b.x,b.y,b.z,b.w};
    union { uint4 u; __half h[8]; } ph, pl;
#pragma unroll
    for (int e=0;e<8;e++){
      __half hh = __float2half_rn(f[e]);
      ph.h[e] = hh;
      pl.h[e] = __float2half_rn(f[e] - __half2float(hh));
    }
    uh = ph.u; ul = pl.u;
  };
  auto stsB = [&](int buf){
#pragma unroll
    for (int s=0;s<2;s++){
      int seg = tid + s*256;
      int row = seg >> 3, sc = seg & 7;
      uint4 uh, ul;
      split8(breg[s][0], breg[s][1], uh, ul);
      char* dst = sm + buf*STAGE + OB + row*SABB + sc*16;
      *reinterpret_cast<uint4*>(dst)       = uh;
      *reinterpret_cast<uint4*>(dst + BBY) = ul;
    }
  };
  auto stsA = [&](int buf){
    int row = tid >> 3, sc = tid & 7;
    uint4 uh, ul;
    split8(areg[0], areg[1], uh, ul);
    char* dst = sm + buf*STAGE + row*SABB + sc*16;
    *reinterpret_cast<uint4*>(dst)       = uh;
    *reinterpret_cast<uint4*>(dst + ABY) = ul;
  };
  auto cpA = [&](int buf, int kb){
    int row = tid >> 3, sc = tid & 7;
    size_t go = (size_t)(m0 + row)*K + kb + sc*8;
    char* d = sm + buf*STAGE + row*SABB + sc*16;
    cp16(d,       Ahi + go);
    cp16(d + ABY, Alo + go);
  };
  auto do_mma = [&](int buf){
    char* sa  = sm + buf*STAGE;
    char* sbh = sa + OB;
    const int ar = lane & 15, ac = (lane >> 4) * 8;
    const int q = lane >> 3, rq = lane & 7;
    const int bro = ((q>>1)*8 + rq)*SABB + (q&1)*16;
#pragma unroll
    for (int ks=0; ks<4; ks++){
      const int kk = ks*16;
      uint32_t ah[4], al[4], bh[4], bl[4];
      char* pa = sa + (wm + ar)*SABB + (kk + ac)*2;
      ldsm4(ah, pa);
      ldsm4(al, pa + ABY);
      char* pb = sbh + wn*SABB + kk*2 + bro;
      ldsm4(bh, pb);
      ldsm4(bl, pb + BBY);
#pragma unroll
      for (int ns=0; ns<2; ns++){
        mma_fp16(acc[ns], ah, bh + ns*2);
        mma_fp16(acc[ns], al, bh + ns*2);
        mma_fp16(acc[ns], ah, bl + ns*2);
      }
    }
  };

  loadB(0); if (A_F32) loadA(0);
  stsB(0);  if (A_F32) stsA(0);
  if (!A_F32){ cpA(0, 0); cp_commit(); }

  for (int i=0; i<nch; i++){
    const int buf = i & 1;
    if (i+1 < nch){ loadB((i+1)*64); if (A_F32) loadA((i+1)*64); }
    if (!A_F32) cp_wait0();
    __syncthreads();
    if (!A_F32 && i+1 < nch){ cpA(buf^1, (i+1)*64); cp_commit(); }
    do_mma(buf);
    if (i+1 < nch){ stsB(buf^1); if (A_F32) stsA(buf^1); }
  }

  const int gr = lane >> 2, gc = (lane & 3) * 2;
#pragma unroll
  for (int ns=0; ns<2; ns++){
    int row = m0 + wm + gr;
    int col = n0 + wn + ns*8 + gc;
    float v0=acc[ns][0], v1=acc[ns][1], v2=acc[ns][2], v3=acc[ns][3];
    float c0=bias[col], c1=bias[col+1];
    v0+=c0; v1+=c1; v2+=c0; v3+=c1;
    if (RELU){ v0=fmaxf(v0,0.f); v1=fmaxf(v1,0.f); v2=fmaxf(v2,0.f); v3=fmaxf(v3,0.f); }
    if (SPLIT){
      __half h0=__float2half_rn(v0), h1=__float2half_rn(v1);
      __half h2=__float2half_rn(v2), h3=__float2half_rn(v3);
      *reinterpret_cast<__half2*>(&Chi[(size_t)row*Ntot + col])     = __halves2half2(h0,h1);
      *reinterpret_cast<__half2*>(&Chi[(size_t)(row+8)*Ntot + col]) = __halves2half2(h2,h3);
      *reinterpret_cast<__half2*>(&Clo[(size_t)row*Ntot + col]) =
          __halves2half2(__float2half_rn(v0-__half2float(h0)), __float2half_rn(v1-__half2float(h1)));
      *reinterpret_cast<__half2*>(&Clo[(size_t)(row+8)*Ntot + col]) =
          __halves2half2(__float2half_rn(v2-__half2float(h2)), __float2half_rn(v3-__half2float(h3)));
    } else {
      *reinterpret_cast<float2*>(&Cf[(size_t)row*Ntot + col])     = make_float2(v0,v1);
      *reinterpret_cast<float2*>(&Cf[(size_t)(row+8)*Ntot + col]) = make_float2(v2,v3);
    }
  }
}

// ===== big GEMM v4: BM=256 (all of M) x BN=128, warp tile 64x64, 1 CTA/SM =====
// smem: A 2-stage (2x20480) + B f16 2-slot (2x10240) = 61440.
// Per ks: 8 ldsm -> 32 mma per warp (1.5x better tensor/L1 ratio than 64x32 tile).
__global__ __launch_bounds__(256, 1)
void hgemmBig(const __half* __restrict__ A, const float* __restrict__ B,
              float* __restrict__ C, int Ntot, int K){
  constexpr int SRS  = 80;                  // f16 row stride (32 halfs + 16B pad)
  constexpr int ABY  = 256*SRS;             // 20480 per A stage
  constexpr int BOFF = 2*ABY;               // 40960 : B f16 slots
  constexpr int BBY  = 128*SRS;             // 10240 per B slot
  constexpr int BK   = 32;

  extern __shared__ __align__(16) char sm[];
  const int tid = threadIdx.x, lane = tid & 31, warp = tid >> 5;
  const int wm = (warp & 3) * 64, wn = (warp >> 2) * 64;   // 4x2 warps, 64x64 tiles
  const int n0 = blockIdx.y * 128;
  const int nch = K / BK;                   // 16

  float acc[4][8][4];
#pragma unroll
  for (int a=0;a<4;a++)
#pragma unroll
    for (int b=0;b<8;b++)
#pragma unroll
      for (int c=0;c<4;c++) acc[a][b][c]=0.f;

  float4 breg[4];
  // B tile: 128 rows x 32 f32 (128B = 8 float4 segs) = 1024 units, 4/thread
  auto loadB = [&](int kb){
#pragma unroll
    for (int s=0;s<4;s++){
      int seg = tid + s*256;
      int row = seg >> 3, q = seg & 7;
      int gn = n0 + row; if (gn > Ntot-1) gn = Ntot-1;
      breg[s] = *reinterpret_cast<const float4*>(B + (size_t)gn*K + kb + q*4);
    }
  };
  auto stsB = [&](int slot){
    char* dst0 = sm + BOFF + slot*BBY;
#pragma unroll
    for (int s=0;s<4;s++){
      int seg = tid + s*256;
      int row = seg >> 3, q = seg & 7;
      union { uint2 u; __half2 h[2]; } o;
      o.h[0] = __floats2half2_rn(breg[s].x, breg[s].y);
      o.h[1] = __floats2half2_rn(breg[s].z, breg[s].w);
      *reinterpret_cast<uint2*>(dst0 + row*SRS + q*8) = o.u;
    }
  };
  auto cpA = [&](int buf, int kb){
    // A fp16: 256 rows x 4 x 16B = 1024 segs, 4/thread
#pragma unroll
    for (int s=0;s<4;s++){
      int seg = tid + s*256;
      int row = seg >> 2, sc = seg & 3;
      cp16(sm + buf*ABY + row*SRS + sc*16, A + (size_t)row*K + kb + sc*8);
    }
    cp_commit();
  };
  auto do_mma = [&](int i){
    char* sa = sm + (i&1)*ABY;
    char* sb = sm + BOFF + (i&1)*BBY;
    const int ar = lane & 15, ac = (lane >> 4) * 8;
    const int q = lane >> 3, rq = lane & 7;
    const int bro = ((q>>1)*8 + rq)*SRS + (q&1)*16;
#pragma unroll
    for (int ks=0; ks<2; ks++){
      const int kk = ks*16;
      uint32_t af[4][4], bf[16];
#pragma unroll
      for (int ms=0; ms<4; ms++)
        ldsm4(af[ms], sa + (wm + ms*16 + ar)*SRS + (kk + ac)*2);
#pragma unroll
      for (int nsp=0; nsp<4; nsp++)
        ldsm4(bf + nsp*4, sb + (wn + nsp*16)*SRS + kk*2 + bro);
#pragma unroll
      for (int ms=0; ms<4; ms++)
#pragma unroll
        for (int ns=0; ns<8; ns++)
          mma_fp16(acc[ms][ns], af[ms], bf + ns*2);
    }
  };

  // prologue: chunk 0 B in smem; A chunk 0 in flight
  loadB(0);
  stsB(0);
  cpA(0, 0);

  for (int i=0; i<nch; i++){
    const int buf = i & 1;
    if (i+1 < nch) loadB((i+1)*BK);   // LDGs for next chunk; consumed after mma(i)
    cp_wait0();                        // A chunk i resident (this thread's view)
    __syncthreads();                   // all threads: A(i)+B(i) visible; mma(i-1)+stsB(i) retired
    if (i+1 < nch) cpA(buf^1, (i+1)*BK);
    do_mma(i);                         // covers LDG latency of loadB(i+1)
    if (i+1 < nch) stsB(buf^1);        // slot (i+1)&1; mma(i-1) that read it retired at sync
  }

  const int gr = lane >> 2, gc = (lane & 3) * 2;
#pragma unroll
  for (int ms=0; ms<4; ms++)
#pragma unroll
    for (int ns=0; ns<8; ns++){
      int row = wm + ms*16 + gr;
      int col = n0 + wn + ns*8 + gc;
      if (col < Ntot){
        *reinterpret_cast<float2*>(&C[(size_t)row*Ntot + col])     = make_float2(acc[ms][ns][0], acc[ms][ns][1]);
        *reinterpret_cast<float2*>(&C[(size_t)(row+8)*Ntot + col]) = make_float2(acc[ms][ns][2], acc[ms][ns][3]);
      }
    }
}

// ---------------- small kernels (round-12 proven) ----------------
__global__ void rownorm_h(const float* __restrict__ img, const float* __restrict__ ls,
                          __half* __restrict__ outh){
  int warp = threadIdx.x >> 5, lane = threadIdx.x & 31;
  int row = blockIdx.x*8 + warp;
  float v[16]; float s = 0.f;
#pragma unroll
  for (int j=0;j<16;j++){ v[j] = img[row*D_OUTF + lane + j*32]; s += v[j]*v[j]; }
#pragma unroll
  for (int off=16; off>0; off>>=1) s += __shfl_xor_sync(0xffffffffu, s, off);
  float sc = expf(*ls) * rsqrtf(s);
#pragma unroll
  for (int j=0;j<16;j++)
    outh[row*D_OUTF + lane + j*32] = __float2half_rn(v[j]*sc);
}

__global__ void topk_p1(const float* __restrict__ logits){
  __shared__ float rv[256];
  __shared__ int   ri[256];
  __shared__ int   sel[TOPK];
  __shared__ float bmax_s;
  int t = threadIdx.x, b = blockIdx.x;
  int lo = b*1000, hi = lo + 1000;

  float vc[4]; int ic[4]; int myn = 0;
  for (int i = lo + t; i < hi; i += 256){ vc[myn] = logits[i]; ic[myn] = i; myn++; }

  float m = -3.4e38f;
  for (int j=0;j<myn;j++) m = fmaxf(m, vc[j]);
  rv[t] = m; __syncthreads();
  for (int s=128; s>0; s>>=1){ if (t<s) rv[t]=fmaxf(rv[t],rv[t+s]); __syncthreads(); }
  if (t==0) bmax_s = rv[0];
  __syncthreads();
  float bm = bmax_s;

  float sum = 0.f;
  for (int j=0;j<myn;j++) sum += expf(vc[j] - bm);
  rv[t] = sum; __syncthreads();
  for (int s=128; s>0; s>>=1){ if (t<s) rv[t]+=rv[t+s]; __syncthreads(); }
  if (t==0){ g_pmax[b] = bm; g_psum[b] = rv[0]; }
  __syncthreads();

  for (int r = 0; r < TOPK; r++){
    float bv = -3.4e38f; int bi = 0x7fffffff;
    for (int j=0;j<myn;j++){
      bool skip = false;
#pragma unroll
      for (int u = 0; u < TOPK; u++) if (u < r && sel[u] == ic[j]) skip = true;
      if (!skip && (vc[j] > bv || (vc[j] == bv && ic[j] < bi))){ bv = vc[j]; bi = ic[j]; }
    }
    rv[t] = bv; ri[t] = bi; __syncthreads();
    for (int s=128; s>0; s>>=1){
      if (t<s){
        if (rv[t+s] > rv[t] || (rv[t+s] == rv[t] && ri[t+s] < ri[t])){
          rv[t]=rv[t+s]; ri[t]=ri[t+s];
        }
      }
      __syncthreads();
    }
    if (t==0){ sel[r] = ri[0]; g_pidx[b*TOPK + r] = ri[0]; g_pval[b*TOPK + r] = rv[0]; }
    __syncthreads();
  }
}

__global__ void topk_p2(const float* __restrict__ gps, float* __restrict__ out_tail){
  __shared__ float rv[512];
  __shared__ int   ri[512];
  __shared__ float gM_s, gS_s;
  int t = threadIdx.x;

  float m = (t < 100) ? g_pmax[t] : -3.4e38f;
  rv[t] = m; __syncthreads();
  for (int s=256; s>0; s>>=1){ if (t<s) rv[t]=fmaxf(rv[t],rv[t+s]); __syncthreads(); }
  if (t==0) gM_s = rv[0];
  __syncthreads();
  float M = gM_s;

  float sum = (t < 100) ? g_psum[t] * expf(g_pmax[t] - M) : 0.f;
  rv[t] = sum; __syncthreads();
  for (int s=256; s>0; s>>=1){ if (t<s) rv[t]+=rv[t+s]; __syncthreads(); }
  if (t==0) gS_s = rv[0];
  __syncthreads();
  float S = gS_s;

  float cv = (t < 100*TOPK) ? g_pval[t] : -3.4e38f;
  int   ci = (t < 100*TOPK) ? g_pidx[t] : 0x7fffffff;

  for (int r = 0; r < TOPK; r++){
    rv[t] = cv; ri[t] = ci; __syncthreads();
    for (int s=256; s>0; s>>=1){
      if (t<s){
        if (rv[t+s] > rv[t] || (rv[t+s] == rv[t] && ri[t+s] < ri[t])){
          rv[t]=rv[t+s]; ri[t]=ri[t+s];
        }
      }
      __syncthreads();
    }
    if (t == 0){
      int gi = ri[0];
      out_tail[2*r]   = gps[2*gi];
      out_tail[2*r+1] = gps[2*gi+1];
      out_tail[2*TOPK + r] = expf(rv[0] - M) / S;
    }
    __syncthreads();
    if (ci == ri[0]) cv = -3.4e38f;
    __syncthreads();
  }
}

extern "C" void kernel_launch(void* const* d_in, const int* in_sizes, int n_in,
                              void* d_out, int out_size){
  const float* img_feats   = (const float*)d_in[0];
  const float* w1          = (const float*)d_in[1];
  const float* b1          = (const float*)d_in[2];
  const float* w2          = (const float*)d_in[3];
  const float* b2          = (const float*)d_in[4];
  const float* logit_scale = (const float*)d_in[5];
  const float* loc_feats   = (const float*)d_in[6];
  const float* gps         = (const float*)d_in[7];
  float* out = (float*)d_out;

  void *ahi2,*alo2,*imgb,*an;
  cudaGetSymbolAddress(&ahi2, g_Ahi2);
  cudaGetSymbolAddress(&alo2, g_Alo2);
  cudaGetSymbolAddress(&imgb, g_IMG);
  cudaGetSymbolAddress(&an,   g_AN);

  cudaFuncSetAttribute(mlpgemm<true,true,true>,    cudaFuncAttributeMaxDynamicSharedMemorySize, 55296);
  cudaFuncSetAttribute(mlpgemm<false,false,false>, cudaFuncAttributeMaxDynamicSharedMemorySize, 55296);
  cudaFuncSetAttribute(hgemmBig,                   cudaFuncAttributeMaxDynamicSharedMemorySize, 61440);

  // 1) H = relu(X W1^T + b1)
  mlpgemm<true,true,true><<<dim3(N_IMG/32, D_HID/64), 256, 55296>>>(
      img_feats, nullptr, nullptr, w1, b1, nullptr, (__half*)ahi2, (__half*)alo2, D_HID, D_INF);
  // 2) IMG = H W2^T + b2
  mlpgemm<false,false,false><<<dim3(N_IMG/32, D_OUTF/64), 256, 55296>>>(
      nullptr, (__half*)ahi2, (__half*)alo2, w2, b2, (float*)imgb, nullptr, nullptr, D_OUTF, D_HID);
  // 3) normalize rows, fold in exp(logit_scale)
  rownorm_h<<<N_IMG/8,256>>>((const float*)imgb, logit_scale, (__half*)an);
  // 4) logits: BM=256 (full M) x BN=128, warp tile 64x64
  hgemmBig<<<dim3(1, (M_GAL+127)/128), 256, 61440>>>(
      (__half*)an, loc_feats, out, M_GAL, D_OUTF);
  // 5) row-0 softmax + top-5
  topk_p1<<<100,256>>>(out);
  topk_p2<<<1,512>>>(gps, out + (size_t)N_IMG*M_GAL);
}

// round 16
// speedup vs baseline: 1.0290x; 1.0290x over previous
#include <cuda_runtime.h>
#include <cuda_fp16.h>
#include <cstdint>

#define DEV __device__ __forceinline__

// problem dims
#define N_IMG 256
#define D_INF 768
#define D_HID 768
#define D_OUTF 512
#define M_GAL 100000
#define TOPK 5

// scratch (no cudaMalloc allowed)
__device__ __half g_Ahi2[N_IMG*D_HID];
__device__ __half g_Alo2[N_IMG*D_HID];
__device__ float  g_IMG [N_IMG*D_OUTF];
__device__ __half g_AN  [N_IMG*D_OUTF];
// topk scratch
__device__ float g_pmax[100];
__device__ float g_psum[100];
__device__ int   g_pidx[100*TOPK];
__device__ float g_pval[100*TOPK];

DEV void cp16(void* s, const void* g){
  uint32_t sa = (uint32_t)__cvta_generic_to_shared(s);
  asm volatile("cp.async.cg.shared.global [%0], [%1], 16;" :: "r"(sa), "l"(g));
}
DEV void cp_commit(){ asm volatile("cp.async.commit_group;"); }
DEV void cp_wait0(){ asm volatile("cp.async.wait_group 0;"); }

DEV void ldsm4(uint32_t* d, const void* p){
  uint32_t a=(uint32_t)__cvta_generic_to_shared(p);
  asm volatile("ldmatrix.sync.aligned.m8n8.x4.shared.b16 {%0,%1,%2,%3}, [%4];"
    : "=r"(d[0]),"=r"(d[1]),"=r"(d[2]),"=r"(d[3]) : "r"(a));
}
DEV void mma_fp16(float* c, const uint32_t* a, const uint32_t* b){
  asm volatile("mma.sync.aligned.m16n8k16.row.col.f32.f16.f16.f32 "
    "{%0,%1,%2,%3}, {%4,%5,%6,%7}, {%8,%9}, {%0,%1,%2,%3};"
    : "+f"(c[0]),"+f"(c[1]),"+f"(c[2]),"+f"(c[3])
    : "r"(a[0]),"r"(a[1]),"r"(a[2]),"r"(a[3]),"r"(b[0]),"r"(b[1]));
}

// ===== MLP GEMM (round-12 proven): 3-term fp16, BM=32 BN=64 BK=64, 2-stage =====
template<bool A_F32, bool RELU, bool SPLIT>
__global__ __launch_bounds__(256, 2)
void mlpgemm(const float* __restrict__ Af, const __half* __restrict__ Ahi, const __half* __restrict__ Alo,
             const float* __restrict__ B, const float* __restrict__ bias,
             float* __restrict__ Cf, __half* __restrict__ Chi, __half* __restrict__ Clo,
             int Ntot, int K){
  constexpr int SABB = 144;
  constexpr int ABY  = 32*SABB;
  constexpr int OB   = 2*ABY;
  constexpr int BBY  = 64*SABB;
  constexpr int STAGE= OB + 2*BBY;   // 27648 ; x2 = 55296

  extern __shared__ __align__(16) char sm[];
  const int tid = threadIdx.x, lane = tid & 31, warp = tid >> 5;
  const int wm = (warp & 1) * 16, wn = (warp >> 1) * 16;
  const int m0 = blockIdx.x * 32, n0 = blockIdx.y * 64;
  const int nch = K / 64;

  float acc[2][4];
#pragma unroll
  for (int b=0;b<2;b++)
#pragma unroll
    for (int c=0;c<4;c++) acc[b][c]=0.f;

  float4 breg[2][2];
  float4 areg[2];
  auto loadB = [&](int kb){
#pragma unroll
    for (int s=0;s<2;s++){
      int seg = tid + s*256;
      int row = seg >> 3, sc = seg & 7;
      const float4* p = reinterpret_cast<const float4*>(B + (size_t)(n0+row)*K + kb + sc*8);
      breg[s][0] = p[0]; breg[s][1] = p[1];
    }
  };
  auto loadA = [&](int kb){
    int row = tid >> 3, sc = tid & 7;
    const float4* p = reinterpret_cast<const float4*>(Af + (size_t)(m0+row)*K + kb + sc*8);
    areg[0] = p[0]; areg[1] = p[1];
  };
  auto split8 = [&](const float4& a, const float4& b, uint4& uh, uint4& ul){
    float f[8] = {a.x,a.y,a.z,a.w,b.x,b.y,b.z,b.w};
    union { uint4 u; __half h[8]; } ph, pl;
#pragma unroll
    for (int e=0;e<8;e++){
      __half hh = __float2half_rn(f[e]);
      ph.h[e] = hh;
      pl.h[e] = __float2half_rn(f[e] - __half2float(hh));
    }
    uh = ph.u; ul = pl.u;
  };
  auto stsB = [&](int buf){
#pragma unroll
    for (int s=0;s<2;s++){
      int seg = tid + s*256;
      int row = seg >> 3, sc = seg & 7;
      uint4 uh, ul;
      split8(breg[s][0], breg[s][1], uh, ul);
      char* dst = sm + buf*STAGE + OB + row*SABB + sc*16;
      *reinterpret_cast<uint4*>(dst)       = uh;
      *reinterpret_cast<uint4*>(dst + BBY) = ul;
    }
  };
  auto stsA = [&](int buf){
    int row = tid >> 3, sc = tid & 7;
    uint4 uh, ul;
    split8(areg[0], areg[1], uh, ul);
    char* dst = sm + buf*STAGE + row*SABB + sc*16;
    *reinterpret_cast<uint4*>(dst)       = uh;
    *reinterpret_cast<uint4*>(dst + ABY) = ul;
  };
  auto cpA = [&](int buf, int kb){
    int row = tid >> 3, sc = tid & 7;
    size_t go = (size_t)(m0 + row)*K + kb + sc*8;
    char* d = sm + buf*STAGE + row*SABB + sc*16;
    cp16(d,       Ahi + go);
    cp16(d + ABY, Alo + go);
  };
  auto do_mma = [&](int buf){
    char* sa  = sm + buf*STAGE;
    char* sbh = sa + OB;
    const int ar = lane & 15, ac = (lane >> 4) * 8;
    const int q = lane >> 3, rq = lane & 7;
    const int bro = ((q>>1)*8 + rq)*SABB + (q&1)*16;
#pragma unroll
    for (int ks=0; ks<4; ks++){
      const int kk = ks*16;
      uint32_t ah[4], al[4], bh[4], bl[4];
      char* pa = sa + (wm + ar)*SABB + (kk + ac)*2;
      ldsm4(ah, pa);
      ldsm4(al, pa + ABY);
      char* pb = sbh + wn*SABB + kk*2 + bro;
      ldsm4(bh, pb);
      ldsm4(bl, pb + BBY);
#pragma unroll
      for (int ns=0; ns<2; ns++){
        mma_fp16(acc[ns], ah, bh + ns*2);
        mma_fp16(acc[ns], al, bh + ns*2);
        mma_fp16(acc[ns], ah, bl + ns*2);
      }
    }
  };

  loadB(0); if (A_F32) loadA(0);
  stsB(0);  if (A_F32) stsA(0);
  if (!A_F32){ cpA(0, 0); cp_commit(); }

  for (int i=0; i<nch; i++){
    const int buf = i & 1;
    if (i+1 < nch){ loadB((i+1)*64); if (A_F32) loadA((i+1)*64); }
    if (!A_F32) cp_wait0();
    __syncthreads();
    if (!A_F32 && i+1 < nch){ cpA(buf^1, (i+1)*64); cp_commit(); }
    do_mma(buf);
    if (i+1 < nch){ stsB(buf^1); if (A_F32) stsA(buf^1); }
  }

  const int gr = lane >> 2, gc = (lane & 3) * 2;
#pragma unroll
  for (int ns=0; ns<2; ns++){
    int row = m0 + wm + gr;
    int col = n0 + wn + ns*8 + gc;
    float v0=acc[ns][0], v1=acc[ns][1], v2=acc[ns][2], v3=acc[ns][3];
    float c0=bias[col], c1=bias[col+1];
    v0+=c0; v1+=c1; v2+=c0; v3+=c1;
    if (RELU){ v0=fmaxf(v0,0.f); v1=fmaxf(v1,0.f); v2=fmaxf(v2,0.f); v3=fmaxf(v3,0.f); }
    if (SPLIT){
      __half h0=__float2half_rn(v0), h1=__float2half_rn(v1);
      __half h2=__float2half_rn(v2), h3=__float2half_rn(v3);
      *reinterpret_cast<__half2*>(&Chi[(size_t)row*Ntot + col])     = __halves2half2(h0,h1);
      *reinterpret_cast<__half2*>(&Chi[(size_t)(row+8)*Ntot + col]) = __halves2half2(h2,h3);
      *reinterpret_cast<__half2*>(&Clo[(size_t)row*Ntot + col]) =
          __halves2half2(__float2half_rn(v0-__half2float(h0)), __float2half_rn(v1-__half2float(h1)));
      *reinterpret_cast<__half2*>(&Clo[(size_t)(row+8)*Ntot + col]) =
          __halves2half2(__float2half_rn(v2-__half2float(h2)), __float2half_rn(v3-__half2float(h3)));
    } else {
      *reinterpret_cast<float2*>(&Cf[(size_t)row*Ntot + col])     = make_float2(v0,v1);
      *reinterpret_cast<float2*>(&Cf[(size_t)(row+8)*Ntot + col]) = make_float2(v2,v3);
    }
  }
}

// ===== big GEMM v5: BM=256 x BN=128, warp tile 64x64, BK=64 (half the barriers) =====
// smem: A 2-stage (2x36864) + B f16 2-slot (2x18432) = 110592. 1 CTA/SM.
// Rationale: 64x64 tile keeps round-15's 1.5x ldsm-traffic win (L1 38.8%); BK=64
// doubles the mma body per barrier (~1200cyc, 4 unrolled ks) so 8 warps suffice.
__global__ __launch_bounds__(256, 1)
void hgemmBig(const __half* __restrict__ A, const float* __restrict__ B,
              float* __restrict__ C, int Ntot, int K){
  constexpr int SRS  = 144;                 // f16 row stride: 64 halfs (128B) + 16B pad
  constexpr int ABY  = 256*SRS;             // 36864 per A stage
  constexpr int BOFF = 2*ABY;               // 73728 : B f16 slots
  constexpr int BBY  = 128*SRS;             // 18432 per B slot
  constexpr int BK   = 64;

  extern __shared__ __align__(16) char sm[];
  const int tid = threadIdx.x, lane = tid & 31, warp = tid >> 5;
  const int wm = (warp & 3) * 64, wn = (warp >> 2) * 64;   // 4x2 warps, 64x64 tiles
  const int n0 = blockIdx.y * 128;
  const int nch = K / BK;                   // 8

  float acc[4][8][4];
#pragma unroll
  for (int a=0;a<4;a++)
#pragma unroll
    for (int b=0;b<8;b++)
#pragma unroll
      for (int c=0;c<4;c++) acc[a][b][c]=0.f;

  float4 breg[8];
  // B tile: 128 rows x 64 f32 (256B = 16 float4 segs) = 2048 units, 8/thread
  auto loadB = [&](int kb){
#pragma unroll
    for (int s=0;s<8;s++){
      int seg = tid + s*256;
      int row = seg >> 4, q = seg & 15;
      int gn = n0 + row; if (gn > Ntot-1) gn = Ntot-1;
      breg[s] = *reinterpret_cast<const float4*>(B + (size_t)gn*K + kb + q*4);
    }
  };
  auto stsB = [&](int slot){
    char* dst0 = sm + BOFF + slot*BBY;
#pragma unroll
    for (int s=0;s<8;s++){
      int seg = tid + s*256;
      int row = seg >> 4, q = seg & 15;
      union { uint2 u; __half2 h[2]; } o;
      o.h[0] = __floats2half2_rn(breg[s].x, breg[s].y);
      o.h[1] = __floats2half2_rn(breg[s].z, breg[s].w);
      *reinterpret_cast<uint2*>(dst0 + row*SRS + q*8) = o.u;   // q*8 <= 120+8=128 <= SRS
    }
  };
  auto cpA = [&](int buf, int kb){
    // A fp16: 256 rows x 8 x 16B = 2048 segs, 8/thread
#pragma unroll
    for (int s=0;s<8;s++){
      int seg = tid + s*256;
      int row = seg >> 3, sc = seg & 7;
      cp16(sm + buf*ABY + row*SRS + sc*16, A + (size_t)row*K + kb + sc*8);
    }
    cp_commit();
  };
  auto do_mma = [&](int i){
    char* sa = sm + (i&1)*ABY;
    char* sb = sm + BOFF + (i&1)*BBY;
    const int ar = lane & 15, ac = (lane >> 4) * 8;
    const int q = lane >> 3, rq = lane & 7;
    const int bro = ((q>>1)*8 + rq)*SRS + (q&1)*16;
#pragma unroll
    for (int ks=0; ks<4; ks++){
      const int kk = ks*16;
      uint32_t af[4][4], bf[16];
#pragma unroll
      for (int ms=0; ms<4; ms++)
        ldsm4(af[ms], sa + (wm + ms*16 + ar)*SRS + (kk + ac)*2);
#pragma unroll
      for (int nsp=0; nsp<4; nsp++)
        ldsm4(bf + nsp*4, sb + (wn + nsp*16)*SRS + kk*2 + bro);
#pragma unroll
      for (int ms=0; ms<4; ms++)
#pragma unroll
        for (int ns=0; ns<8; ns++)
          mma_fp16(acc[ms][ns], af[ms], bf + ns*2);
    }
  };

  // prologue: chunk 0 B in smem; A chunk 0 in flight
  loadB(0);
  stsB(0);
  cpA(0, 0);

  for (int i=0; i<nch; i++){
    const int buf = i & 1;
    if (i+1 < nch) loadB((i+1)*BK);   // LDGs for next chunk; consumed after mma(i)
    cp_wait0();                        // A chunk i resident (only 1 group in flight)
    __syncthreads();                   // all threads: A(i)+B(i) visible; mma(i-1)+stsB(i) retired
    if (i+1 < nch) cpA(buf^1, (i+1)*BK);
    do_mma(i);                         // ~1200cyc body covers loadB(i+1) LDG latency
    if (i+1 < nch) stsB(buf^1);        // slot (i+1)&1; mma(i-1) that read it retired at sync
  }

  const int gr = lane >> 2, gc = (lane & 3) * 2;
#pragma unroll
  for (int ms=0; ms<4; ms++)
#pragma unroll
    for (int ns=0; ns<8; ns++){
      int row = wm + ms*16 + gr;
      int col = n0 + wn + ns*8 + gc;
      if (col < Ntot){
        *reinterpret_cast<float2*>(&C[(size_t)row*Ntot + col])     = make_float2(acc[ms][ns][0], acc[ms][ns][1]);
        *reinterpret_cast<float2*>(&C[(size_t)(row+8)*Ntot + col]) = make_float2(acc[ms][ns][2], acc[ms][ns][3]);
      }
    }
}

// ---------------- small kernels (round-12 proven) ----------------
__global__ void rownorm_h(const float* __restrict__ img, const float* __restrict__ ls,
                          __half* __restrict__ outh){
  int warp = threadIdx.x >> 5, lane = threadIdx.x & 31;
  int row = blockIdx.x*8 + warp;
  float v[16]; float s = 0.f;
#pragma unroll
  for (int j=0;j<16;j++){ v[j] = img[row*D_OUTF + lane + j*32]; s += v[j]*v[j]; }
#pragma unroll
  for (int off=16; off>0; off>>=1) s += __shfl_xor_sync(0xffffffffu, s, off);
  float sc = expf(*ls) * rsqrtf(s);
#pragma unroll
  for (int j=0;j<16;j++)
    outh[row*D_OUTF + lane + j*32] = __float2half_rn(v[j]*sc);
}

__global__ void topk_p1(const float* __restrict__ logits){
  __shared__ float rv[256];
  __shared__ int   ri[256];
  __shared__ int   sel[TOPK];
  __shared__ float bmax_s;
  int t = threadIdx.x, b = blockIdx.x;
  int lo = b*1000, hi = lo + 1000;

  float vc[4]; int ic[4]; int myn = 0;
  for (int i = lo + t; i < hi; i += 256){ vc[myn] = logits[i]; ic[myn] = i; myn++; }

  float m = -3.4e38f;
  for (int j=0;j<myn;j++) m = fmaxf(m, vc[j]);
  rv[t] = m; __syncthreads();
  for (int s=128; s>0; s>>=1){ if (t<s) rv[t]=fmaxf(rv[t],rv[t+s]); __syncthreads(); }
  if (t==0) bmax_s = rv[0];
  __syncthreads();
  float bm = bmax_s;

  float sum = 0.f;
  for (int j=0;j<myn;j++) sum += expf(vc[j] - bm);
  rv[t] = sum; __syncthreads();
  for (int s=128; s>0; s>>=1){ if (t<s) rv[t]+=rv[t+s]; __syncthreads(); }
  if (t==0){ g_pmax[b] = bm; g_psum[b] = rv[0]; }
  __syncthreads();

  for (int r = 0; r < TOPK; r++){
    float bv = -3.4e38f; int bi = 0x7fffffff;
    for (int j=0;j<myn;j++){
      bool skip = false;
#pragma unroll
      for (int u = 0; u < TOPK; u++) if (u < r && sel[u] == ic[j]) skip = true;
      if (!skip && (vc[j] > bv || (vc[j] == bv && ic[j] < bi))){ bv = vc[j]; bi = ic[j]; }
    }
    rv[t] = bv; ri[t] = bi; __syncthreads();
    for (int s=128; s>0; s>>=1){
      if (t<s){
        if (rv[t+s] > rv[t] || (rv[t+s] == rv[t] && ri[t+s] < ri[t])){
          rv[t]=rv[t+s]; ri[t]=ri[t+s];
        }
      }
      __syncthreads();
    }
    if (t==0){ sel[r] = ri[0]; g_pidx[b*TOPK + r] = ri[0]; g_pval[b*TOPK + r] = rv[0]; }
    __syncthreads();
  }
}

__global__ void topk_p2(const float* __restrict__ gps, float* __restrict__ out_tail){
  __shared__ float rv[512];
  __shared__ int   ri[512];
  __shared__ float gM_s, gS_s;
  int t = threadIdx.x;

  float m = (t < 100) ? g_pmax[t] : -3.4e38f;
  rv[t] = m; __syncthreads();
  for (int s=256; s>0; s>>=1){ if (t<s) rv[t]=fmaxf(rv[t],rv[t+s]); __syncthreads(); }
  if (t==0) gM_s = rv[0];
  __syncthreads();
  float M = gM_s;

  float sum = (t < 100) ? g_psum[t] * expf(g_pmax[t] - M) : 0.f;
  rv[t] = sum; __syncthreads();
  for (int s=256; s>0; s>>=1){ if (t<s) rv[t]+=rv[t+s]; __syncthreads(); }
  if (t==0) gS_s = rv[0];
  __syncthreads();
  float S = gS_s;

  float cv = (t < 100*TOPK) ? g_pval[t] : -3.4e38f;
  int   ci = (t < 100*TOPK) ? g_pidx[t] : 0x7fffffff;

  for (int r = 0; r < TOPK; r++){
    rv[t] = cv; ri[t] = ci; __syncthreads();
    for (int s=256; s>0; s>>=1){
      if (t<s){
        if (rv[t+s] > rv[t] || (rv[t+s] == rv[t] && ri[t+s] < ri[t])){
          rv[t]=rv[t+s]; ri[t]=ri[t+s];
        }
      }
      __syncthreads();
    }
    if (t == 0){
      int gi = ri[0];
      out_tail[2*r]   = gps[2*gi];
      out_tail[2*r+1] = gps[2*gi+1];
      out_tail[2*TOPK + r] = expf(rv[0] - M) / S;
    }
    __syncthreads();
    if (ci == ri[0]) cv = -3.4e38f;
    __syncthreads();
  }
}

extern "C" void kernel_launch(void* const* d_in, const int* in_sizes, int n_in,
                              void* d_out, int out_size){
  const float* img_feats   = (const float*)d_in[0];
  const float* w1          = (const float*)d_in[1];
  const float* b1          = (const float*)d_in[2];
  const float* w2          = (const float*)d_in[3];
  const float* b2          = (const float*)d_in[4];
  const float* logit_scale = (const float*)d_in[5];
  const float* loc_feats   = (const float*)d_in[6];
  const float* gps         = (const float*)d_in[7];
  float* out = (float*)d_out;

  void *ahi2,*alo2,*imgb,*an;
  cudaGetSymbolAddress(&ahi2, g_Ahi2);
  cudaGetSymbolAddress(&alo2, g_Alo2);
  cudaGetSymbolAddress(&imgb, g_IMG);
  cudaGetSymbolAddress(&an,   g_AN);

  cudaFuncSetAttribute(mlpgemm<true,true,true>,    cudaFuncAttributeMaxDynamicSharedMemorySize, 55296);
  cudaFuncSetAttribute(mlpgemm<false,false,false>, cudaFuncAttributeMaxDynamicSharedMemorySize, 55296);
  cudaFuncSetAttribute(hgemmBig,                   cudaFuncAttributeMaxDynamicSharedMemorySize, 110592);

  // 1) H = relu(X W1^T + b1)
  mlpgemm<true,true,true><<<dim3(N_IMG/32, D_HID/64), 256, 55296>>>(
      img_feats, nullptr, nullptr, w1, b1, nullptr, (__half*)ahi2, (__half*)alo2, D_HID, D_INF);
  // 2) IMG = H W2^T + b2
  mlpgemm<false,false,false><<<dim3(N_IMG/32, D_OUTF/64), 256, 55296>>>(
      nullptr, (__half*)ahi2, (__half*)alo2, w2, b2, (float*)imgb, nullptr, nullptr, D_OUTF, D_HID);
  // 3) normalize rows, fold in exp(logit_scale)
  rownorm_h<<<N_IMG/8,256>>>((const float*)imgb, logit_scale, (__half*)an);
  // 4) logits: BM=256 x BN=128, warp tile 64x64, BK=64
  hgemmBig<<<dim3(1, (M_GAL+127)/128), 256, 110592>>>(
      (__half*)an, loc_feats, out, M_GAL, D_OUTF);
  // 5) row-0 softmax + top-5
  topk_p1<<<100,256>>>(out);
  topk_p2<<<1,512>>>(gps, out + (size_t)N_IMG*M_GAL);
}

// round 17
// speedup vs baseline: 1.0677x; 1.0376x over previous
#include <cuda_runtime.h>
#include <cuda_fp16.h>
#include <cstdint>

#define DEV __device__ __forceinline__

// problem dims
#define N_IMG 256
#define D_INF 768
#define D_HID 768
#define D_OUTF 512
#define M_GAL 100000
#define TOPK 5

// scratch (no cudaMalloc allowed)
__device__ __half g_Ahi2[N_IMG*D_HID];
__device__ __half g_Alo2[N_IMG*D_HID];
__device__ float  g_IMG [N_IMG*D_OUTF];
__device__ __half g_AN  [N_IMG*D_OUTF];
// topk scratch
__device__ float g_pmax[100];
__device__ float g_psum[100];
__device__ int   g_pidx[100*TOPK];
__device__ float g_pval[100*TOPK];

DEV void cp16(void* s, const void* g){
  uint32_t sa = (uint32_t)__cvta_generic_to_shared(s);
  asm volatile("cp.async.cg.shared.global [%0], [%1], 16;" :: "r"(sa), "l"(g));
}
DEV void cp_commit(){ asm volatile("cp.async.commit_group;"); }
DEV void cp_wait0(){ asm volatile("cp.async.wait_group 0;"); }

DEV void ldsm4(uint32_t* d, const void* p){
  uint32_t a=(uint32_t)__cvta_generic_to_shared(p);
  asm volatile("ldmatrix.sync.aligned.m8n8.x4.shared.b16 {%0,%1,%2,%3}, [%4];"
    : "=r"(d[0]),"=r"(d[1]),"=r"(d[2]),"=r"(d[3]) : "r"(a));
}
DEV void mma_fp16(float* c, const uint32_t* a, const uint32_t* b){
  asm volatile("mma.sync.aligned.m16n8k16.row.col.f32.f16.f16.f32 "
    "{%0,%1,%2,%3}, {%4,%5,%6,%7}, {%8,%9}, {%0,%1,%2,%3};"
    : "+f"(c[0]),"+f"(c[1]),"+f"(c[2]),"+f"(c[3])
    : "r"(a[0]),"r"(a[1]),"r"(a[2]),"r"(a[3]),"r"(b[0]),"r"(b[1]));
}

// ===== MLP GEMM (round-12 proven): 3-term fp16, BM=32 BN=64 BK=64, 2-stage =====
template<bool A_F32, bool RELU, bool SPLIT>
__global__ __launch_bounds__(256, 2)
void mlpgemm(const float* __restrict__ Af, const __half* __restrict__ Ahi, const __half* __restrict__ Alo,
             const float* __restrict__ B, const float* __restrict__ bias,
             float* __restrict__ Cf, __half* __restrict__ Chi, __half* __restrict__ Clo,
             int Ntot, int K){
  constexpr int SABB = 144;
  constexpr int ABY  = 32*SABB;
  constexpr int OB   = 2*ABY;
  constexpr int BBY  = 64*SABB;
  constexpr int STAGE= OB + 2*BBY;   // 27648 ; x2 = 55296

  extern __shared__ __align__(16) char sm[];
  const int tid = threadIdx.x, lane = tid & 31, warp = tid >> 5;
  const int wm = (warp & 1) * 16, wn = (warp >> 1) * 16;
  const int m0 = blockIdx.x * 32, n0 = blockIdx.y * 64;
  const int nch = K / 64;

  float acc[2][4];
#pragma unroll
  for (int b=0;b<2;b++)
#pragma unroll
    for (int c=0;c<4;c++) acc[b][c]=0.f;

  float4 breg[2][2];
  float4 areg[2];
  auto loadB = [&](int kb){
#pragma unroll
    for (int s=0;s<2;s++){
      int seg = tid + s*256;
      int row = seg >> 3, sc = seg & 7;
      const float4* p = reinterpret_cast<const float4*>(B + (size_t)(n0+row)*K + kb + sc*8);
      breg[s][0] = p[0]; breg[s][1] = p[1];
    }
  };
  auto loadA = [&](int kb){
    int row = tid >> 3, sc = tid & 7;
    const float4* p = reinterpret_cast<const float4*>(Af + (size_t)(m0+row)*K + kb + sc*8);
    areg[0] = p[0]; areg[1] = p[1];
  };
  auto split8 = [&](const float4& a, const float4& b, uint4& uh, uint4& ul){
    float f[8] = {a.x,a.y,a.z,a.w,b.x,b.y,b.z,b.w};
    union { uint4 u; __half h[8]; } ph, pl;
#pragma unroll
    for (int e=0;e<8;e++){
      __half hh = __float2half_rn(f[e]);
      ph.h[e] = hh;
      pl.h[e] = __float2half_rn(f[e] - __half2float(hh));
    }
    uh = ph.u; ul = pl.u;
  };
  auto stsB = [&](int buf){
#pragma unroll
    for (int s=0;s<2;s++){
      int seg = tid + s*256;
      int row = seg >> 3, sc = seg & 7;
      uint4 uh, ul;
      split8(breg[s][0], breg[s][1], uh, ul);
      char* dst = sm + buf*STAGE + OB + row*SABB + sc*16;
      *reinterpret_cast<uint4*>(dst)       = uh;
      *reinterpret_cast<uint4*>(dst + BBY) = ul;
    }
  };
  auto stsA = [&](int buf){
    int row = tid >> 3, sc = tid & 7;
    uint4 uh, ul;
    split8(areg[0], areg[1], uh, ul);
    char* dst = sm + buf*STAGE + row*SABB + sc*16;
    *reinterpret_cast<uint4*>(dst)       = uh;
    *reinterpret_cast<uint4*>(dst + ABY) = ul;
  };
  auto cpA = [&](int buf, int kb){
    int row = tid >> 3, sc = tid & 7;
    size_t go = (size_t)(m0 + row)*K + kb + sc*8;
    char* d = sm + buf*STAGE + row*SABB + sc*16;
    cp16(d,       Ahi + go);
    cp16(d + ABY, Alo + go);
  };
  auto do_mma = [&](int buf){
    char* sa  = sm + buf*STAGE;
    char* sbh = sa + OB;
    const int ar = lane & 15, ac = (lane >> 4) * 8;
    const int q = lane >> 3, rq = lane & 7;
    const int bro = ((q>>1)*8 + rq)*SABB + (q&1)*16;
#pragma unroll
    for (int ks=0; ks<4; ks++){
      const int kk = ks*16;
      uint32_t ah[4], al[4], bh[4], bl[4];
      char* pa = sa + (wm + ar)*SABB + (kk + ac)*2;
      ldsm4(ah, pa);
      ldsm4(al, pa + ABY);
      char* pb = sbh + wn*SABB + kk*2 + bro;
      ldsm4(bh, pb);
      ldsm4(bl, pb + BBY);
#pragma unroll
      for (int ns=0; ns<2; ns++){
        mma_fp16(acc[ns], ah, bh + ns*2);
        mma_fp16(acc[ns], al, bh + ns*2);
        mma_fp16(acc[ns], ah, bl + ns*2);
      }
    }
  };

  loadB(0); if (A_F32) loadA(0);
  stsB(0);  if (A_F32) stsA(0);
  if (!A_F32){ cpA(0, 0); cp_commit(); }

  for (int i=0; i<nch; i++){
    const int buf = i & 1;
    if (i+1 < nch){ loadB((i+1)*64); if (A_F32) loadA((i+1)*64); }
    if (!A_F32) cp_wait0();
    __syncthreads();
    if (!A_F32 && i+1 < nch){ cpA(buf^1, (i+1)*64); cp_commit(); }
    do_mma(buf);
    if (i+1 < nch){ stsB(buf^1); if (A_F32) stsA(buf^1); }
  }

  const int gr = lane >> 2, gc = (lane & 3) * 2;
#pragma unroll
  for (int ns=0; ns<2; ns++){
    int row = m0 + wm + gr;
    int col = n0 + wn + ns*8 + gc;
    float v0=acc[ns][0], v1=acc[ns][1], v2=acc[ns][2], v3=acc[ns][3];
    float c0=bias[col], c1=bias[col+1];
    v0+=c0; v1+=c1; v2+=c0; v3+=c1;
    if (RELU){ v0=fmaxf(v0,0.f); v1=fmaxf(v1,0.f); v2=fmaxf(v2,0.f); v3=fmaxf(v3,0.f); }
    if (SPLIT){
      __half h0=__float2half_rn(v0), h1=__float2half_rn(v1);
      __half h2=__float2half_rn(v2), h3=__float2half_rn(v3);
      *reinterpret_cast<__half2*>(&Chi[(size_t)row*Ntot + col])     = __halves2half2(h0,h1);
      *reinterpret_cast<__half2*>(&Chi[(size_t)(row+8)*Ntot + col]) = __halves2half2(h2,h3);
      *reinterpret_cast<__half2*>(&Clo[(size_t)row*Ntot + col]) =
          __halves2half2(__float2half_rn(v0-__half2float(h0)), __float2half_rn(v1-__half2float(h1)));
      *reinterpret_cast<__half2*>(&Clo[(size_t)(row+8)*Ntot + col]) =
          __halves2half2(__float2half_rn(v2-__half2float(h2)), __float2half_rn(v3-__half2float(h3)));
    } else {
      *reinterpret_cast<float2*>(&Cf[(size_t)row*Ntot + col])     = make_float2(v0,v1);
      *reinterpret_cast<float2*>(&Cf[(size_t)(row+8)*Ntot + col]) = make_float2(v2,v3);
    }
  }
}

// ===== big GEMM v6: R14 shape (BM128 BN128, warp 64x32, 2 CTA/SM) + BK=64 =====
// B loaded in TWO half-chunks (breg stays 4 float4 -> regs ~126, no spill),
// interleaved with the two mma halves. Barriers per CTA: 8 (vs R14's 16).
__global__ __launch_bounds__(256, 2)
void hgemmBig(const __half* __restrict__ A, const float* __restrict__ B,
              float* __restrict__ C, int Ntot, int K){
  constexpr int SRS  = 144;                 // 64 halfs (128B) + 16B pad
  constexpr int ABY  = 128*SRS;             // 18432 per A stage
  constexpr int BOFF = 2*ABY;               // 36864 : B f16 slots
  constexpr int BBY  = 128*SRS;             // 18432 per B slot; total 73728
  constexpr int BK   = 64;

  extern __shared__ __align__(16) char sm[];
  const int tid = threadIdx.x, lane = tid & 31, warp = tid >> 5;
  const int wm = (warp & 1) * 64, wn = (warp >> 1) * 32;   // 2x4 warps, 64x32 tiles
  const int m0 = blockIdx.x * 128, n0 = blockIdx.y * 128;
  const int nch = K / BK;                   // 8

  float acc[4][4][4];
#pragma unroll
  for (int a=0;a<4;a++)
#pragma unroll
    for (int b=0;b<4;b++)
#pragma unroll
      for (int c=0;c<4;c++) acc[a][b][c]=0.f;

  float4 breg[4];
  // B half: 128 rows x 32 f32 (128B = 8 float4 segs) = 1024 units, 4/thread
  auto loadBh = [&](int h, int kb){
#pragma unroll
    for (int s=0;s<4;s++){
      int seg = tid + s*256;
      int row = seg >> 3, q = seg & 7;
      int gn = n0 + row; if (gn > Ntot-1) gn = Ntot-1;
      breg[s] = *reinterpret_cast<const float4*>(B + (size_t)gn*K + kb + h*32 + q*4);
    }
  };
  auto stsBh = [&](int h, int slot){
    char* dst0 = sm + BOFF + slot*BBY;
#pragma unroll
    for (int s=0;s<4;s++){
      int seg = tid + s*256;
      int row = seg >> 3, q = seg & 7;
      union { uint2 u; __half2 hh[2]; } o;
      o.hh[0] = __floats2half2_rn(breg[s].x, breg[s].y);
      o.hh[1] = __floats2half2_rn(breg[s].z, breg[s].w);
      *reinterpret_cast<uint2*>(dst0 + row*SRS + h*64 + q*8) = o.u;  // max 127*144+64+64 <= BBY
    }
  };
  auto cpA = [&](int buf, int kb){
    // A fp16: 128 rows x 8 x 16B = 1024 segs, 4/thread
#pragma unroll
    for (int s=0;s<4;s++){
      int seg = tid + s*256;
      int row = seg >> 3, sc = seg & 7;
      cp16(sm + buf*ABY + row*SRS + sc*16, A + (size_t)(m0 + row)*K + kb + sc*8);
    }
    cp_commit();
  };
  auto do_mma_h = [&](int i, int h){
    char* sa = sm + (i&1)*ABY;
    char* sb = sm + BOFF + (i&1)*BBY;
    const int ar = lane & 15, ac = (lane >> 4) * 8;
    const int q = lane >> 3, rq = lane & 7;
    const int bro = ((q>>1)*8 + rq)*SRS + (q&1)*16;
#pragma unroll
    for (int ks=0; ks<2; ks++){
      const int kk = h*32 + ks*16;
      uint32_t af[4][4], bf[8];
#pragma unroll
      for (int ms=0; ms<4; ms++)
        ldsm4(af[ms], sa + (wm + ms*16 + ar)*SRS + (kk + ac)*2);
#pragma unroll
      for (int nsp=0; nsp<2; nsp++)
        ldsm4(bf + nsp*4, sb + (wn + nsp*16)*SRS + kk*2 + bro);
#pragma unroll
      for (int ms=0; ms<4; ms++)
#pragma unroll
        for (int ns=0; ns<4; ns++)
          mma_fp16(acc[ms][ns], af[ms], bf + ns*2);
    }
  };

  // prologue: chunk 0 B fully in smem; A chunk 0 in flight
  loadBh(0, 0); stsBh(0, 0);
  loadBh(1, 0); stsBh(1, 0);
  cpA(0, 0);

  for (int i=0; i<nch; i++){
    const int buf = i & 1;
    if (i+1 < nch) loadBh(0, (i+1)*BK);   // LDG h0 of next chunk
    cp_wait0();                            // A chunk i resident (this thread)
    __syncthreads();                       // A(i)+B(i) visible; mma(i-1)+stsB(i) retired
    if (i+1 < nch) cpA(buf^1, (i+1)*BK);
    do_mma_h(i, 0);                        // ks 0,1 — covers h0 LDG latency
    if (i+1 < nch){
      stsBh(0, buf^1);                     // slot (i+1)&1: last read by mma(i-1), retired
      loadBh(1, (i+1)*BK);                 // LDG h1 of next chunk
    }
    do_mma_h(i, 1);                        // ks 2,3 — covers h1 LDG latency
    if (i+1 < nch) stsBh(1, buf^1);
  }

  const int gr = lane >> 2, gc = (lane & 3) * 2;
#pragma unroll
  for (int ms=0; ms<4; ms++)
#pragma unroll
    for (int ns=0; ns<4; ns++){
      int row = m0 + wm + ms*16 + gr;
      int col = n0 + wn + ns*8 + gc;
      if (col < Ntot){
        *reinterpret_cast<float2*>(&C[(size_t)row*Ntot + col])     = make_float2(acc[ms][ns][0], acc[ms][ns][1]);
        *reinterpret_cast<float2*>(&C[(size_t)(row+8)*Ntot + col]) = make_float2(acc[ms][ns][2], acc[ms][ns][3]);
      }
    }
}

// ---------------- small kernels (round-12 proven) ----------------
__global__ void rownorm_h(const float* __restrict__ img, const float* __restrict__ ls,
                          __half* __restrict__ outh){
  int warp = threadIdx.x >> 5, lane = threadIdx.x & 31;
  int row = blockIdx.x*8 + warp;
  float v[16]; float s = 0.f;
#pragma unroll
  for (int j=0;j<16;j++){ v[j] = img[row*D_OUTF + lane + j*32]; s += v[j]*v[j]; }
#pragma unroll
  for (int off=16; off>0; off>>=1) s += __shfl_xor_sync(0xffffffffu, s, off);
  float sc = expf(*ls) * rsqrtf(s);
#pragma unroll
  for (int j=0;j<16;j++)
    outh[row*D_OUTF + lane + j*32] = __float2half_rn(v[j]*sc);
}

__global__ void topk_p1(const float* __restrict__ logits){
  __shared__ float rv[256];
  __shared__ int   ri[256];
  __shared__ int   sel[TOPK];
  __shared__ float bmax_s;
  int t = threadIdx.x, b = blockIdx.x;
  int lo = b*1000, hi = lo + 1000;

  float vc[4]; int ic[4]; int myn = 0;
  for (int i = lo + t; i < hi; i += 256){ vc[myn] = logits[i]; ic[myn] = i; myn++; }

  float m = -3.4e38f;
  for (int j=0;j<myn;j++) m = fmaxf(m, vc[j]);
  rv[t] = m; __syncthreads();
  for (int s=128; s>0; s>>=1){ if (t<s) rv[t]=fmaxf(rv[t],rv[t+s]); __syncthreads(); }
  if (t==0) bmax_s = rv[0];
  __syncthreads();
  float bm = bmax_s;

  float sum = 0.f;
  for (int j=0;j<myn;j++) sum += expf(vc[j] - bm);
  rv[t] = sum; __syncthreads();
  for (int s=128; s>0; s>>=1){ if (t<s) rv[t]+=rv[t+s]; __syncthreads(); }
  if (t==0){ g_pmax[b] = bm; g_psum[b] = rv[0]; }
  __syncthreads();

  for (int r = 0; r < TOPK; r++){
    float bv = -3.4e38f; int bi = 0x7fffffff;
    for (int j=0;j<myn;j++){
      bool skip = false;
#pragma unroll
      for (int u = 0; u < TOPK; u++) if (u < r && sel[u] == ic[j]) skip = true;
      if (!skip && (vc[j] > bv || (vc[j] == bv && ic[j] < bi))){ bv = vc[j]; bi = ic[j]; }
    }
    rv[t] = bv; ri[t] = bi; __syncthreads();
    for (int s=128; s>0; s>>=1){
      if (t<s){
        if (rv[t+s] > rv[t] || (rv[t+s] == rv[t] && ri[t+s] < ri[t])){
          rv[t]=rv[t+s]; ri[t]=ri[t+s];
        }
      }
      __syncthreads();
    }
    if (t==0){ sel[r] = ri[0]; g_pidx[b*TOPK + r] = ri[0]; g_pval[b*TOPK + r] = rv[0]; }
    __syncthreads();
  }
}

__global__ void topk_p2(const float* __restrict__ gps, float* __restrict__ out_tail){
  __shared__ float rv[512];
  __shared__ int   ri[512];
  __shared__ float gM_s, gS_s;
  int t = threadIdx.x;

  float m = (t < 100) ? g_pmax[t] : -3.4e38f;
  rv[t] = m; __syncthreads();
  for (int s=256; s>0; s>>=1){ if (t<s) rv[t]=fmaxf(rv[t],rv[t+s]); __syncthreads(); }
  if (t==0) gM_s = rv[0];
  __syncthreads();
  float M = gM_s;

  float sum = (t < 100) ? g_psum[t] * expf(g_pmax[t] - M) : 0.f;
  rv[t] = sum; __syncthreads();
  for (int s=256; s>0; s>>=1){ if (t<s) rv[t]+=rv[t+s]; __syncthreads(); }
  if (t==0) gS_s = rv[0];
  __syncthreads();
  float S = gS_s;

  float cv = (t < 100*TOPK) ? g_pval[t] : -3.4e38f;
  int   ci = (t < 100*TOPK) ? g_pidx[t] : 0x7fffffff;

  for (int r = 0; r < TOPK; r++){
    rv[t] = cv; ri[t] = ci; __syncthreads();
    for (int s=256; s>0; s>>=1){
      if (t<s){
        if (rv[t+s] > rv[t] || (rv[t+s] == rv[t] && ri[t+s] < ri[t])){
          rv[t]=rv[t+s]; ri[t]=ri[t+s];
        }
      }
      __syncthreads();
    }
    if (t == 0){
      int gi = ri[0];
      out_tail[2*r]   = gps[2*gi];
      out_tail[2*r+1] = gps[2*gi+1];
      out_tail[2*TOPK + r] = expf(rv[0] - M) / S;
    }
    __syncthreads();
    if (ci == ri[0]) cv = -3.4e38f;
    __syncthreads();
  }
}

extern "C" void kernel_launch(void* const* d_in, const int* in_sizes, int n_in,
                              void* d_out, int out_size){
  const float* img_feats   = (const float*)d_in[0];
  const float* w1          = (const float*)d_in[1];
  const float* b1          = (const float*)d_in[2];
  const float* w2          = (const float*)d_in[3];
  const float* b2          = (const float*)d_in[4];
  const float* logit_scale = (const float*)d_in[5];
  const float* loc_feats   = (const float*)d_in[6];
  const float* gps         = (const float*)d_in[7];
  float* out = (float*)d_out;

  void *ahi2,*alo2,*imgb,*an;
  cudaGetSymbolAddress(&ahi2, g_Ahi2);
  cudaGetSymbolAddress(&alo2, g_Alo2);
  cudaGetSymbolAddress(&imgb, g_IMG);
  cudaGetSymbolAddress(&an,   g_AN);

  cudaFuncSetAttribute(mlpgemm<true,true,true>,    cudaFuncAttributeMaxDynamicSharedMemorySize, 55296);
  cudaFuncSetAttribute(mlpgemm<false,false,false>, cudaFuncAttributeMaxDynamicSharedMemorySize, 55296);
  cudaFuncSetAttribute(hgemmBig,                   cudaFuncAttributeMaxDynamicSharedMemorySize, 73728);

  // 1) H = relu(X W1^T + b1)
  mlpgemm<true,true,true><<<dim3(N_IMG/32, D_HID/64), 256, 55296>>>(
      img_feats, nullptr, nullptr, w1, b1, nullptr, (__half*)ahi2, (__half*)alo2, D_HID, D_INF);
  // 2) IMG = H W2^T + b2
  mlpgemm<false,false,false><<<dim3(N_IMG/32, D_OUTF/64), 256, 55296>>>(
      nullptr, (__half*)ahi2, (__half*)alo2, w2, b2, (float*)imgb, nullptr, nullptr, D_OUTF, D_HID);
  // 3) normalize rows, fold in exp(logit_scale)
  rownorm_h<<<N_IMG/8,256>>>((const float*)imgb, logit_scale, (__half*)an);
  // 4) logits: R14 shape + BK=64, half-chunk B loads (8 barriers instead of 16)
  hgemmBig<<<dim3(2, (M_GAL+127)/128), 256, 73728>>>(
      (__half*)an, loc_feats, out, M_GAL, D_OUTF);
  // 5) row-0 softmax + top-5
  topk_p1<<<100,256>>>(out);
  topk_p2<<<1,512>>>(gps, out + (size_t)N_IMG*M_GAL);
}